// round 6
// baseline (speedup 1.0000x reference)
#include <cuda_runtime.h>
#include <cuda_bf16.h>
#include <cstdint>

// emb = (mask @ mlp_out)/max(cnt,1), mlp_out = relu(idx@W1+b1)@W2 + b2
// Factorized GEMM: D[128 x 40] = mask_tile[128 x 2048] @ hE[40 x 2048]^T via
// mma.sync.m16n8k16 bf16 (sm_80 baseline feature — compute_103-safe).
// hE rows: 0-15 bf16_hi(h), 16-31 bf16(h-hi) residual, 32 ones (count), 33-39 zero.
// A (mask) streamed fp32 via cp.async into double-buffered smem chunks, converted
// to exact 0/1 bf16 in registers at fragment-build time.

#define S        2000
#define SP       2048
#define HDIM     16
#define NB       40
#define EDIM     128
#define TILE_M   128
#define THREADS  256
#define KCH      32          // A chunk K
#define NKCH     64          // SP/KCH
#define BS_K     256         // B chunk K
#define BS_STR   264         // bf16 stride (pad kills bank conflicts)

// smem byte offsets
#define A0_OFF   0           // 128*32*4 = 16384
#define A1_OFF   16384
#define BS_OFF   32768       // 40*264*2 = 21120 -> ends 53888
#define W2_OFF   53888       // 8192
#define B2_OFF   62080       // 512
#define SMEM_SZ  62592

__device__ __nv_bfloat16 g_hE[NB * SP];

__global__ void build_hE(const float* __restrict__ W1,
                         const float* __restrict__ b1) {
    int i = blockIdx.x * blockDim.x + threadIdx.x;
    if (i >= NB * SP) return;
    int n = i / SP;
    int s = i - n * SP;
    float v = 0.0f;
    if (s < S) {
        if (n < HDIM) {
            float h = fmaf((float)s, W1[n], b1[n]);
            h = h > 0.0f ? h : 0.0f;
            v = __bfloat162float(__float2bfloat16(h));
        } else if (n < 2 * HDIM) {
            int d = n - HDIM;
            float h = fmaf((float)s, W1[d], b1[d]);
            h = h > 0.0f ? h : 0.0f;
            v = h - __bfloat162float(__float2bfloat16(h));
        } else if (n == 2 * HDIM) {
            v = 1.0f;
        }
    }
    g_hE[n * SP + s] = __float2bfloat16(v);
}

__device__ __forceinline__ uint32_t smem_u32(const void* p) {
    uint32_t a;
    asm("{ .reg .u64 t; cvta.to.shared.u64 t, %1; cvt.u32.u64 %0, t; }"
        : "=r"(a) : "l"(p));
    return a;
}
__device__ __forceinline__ void cp_async16(uint32_t dst, const void* src, uint32_t sz) {
    asm volatile("cp.async.cg.shared.global [%0], [%1], 16, %2;\n"
                 :: "r"(dst), "l"(src), "r"(sz) : "memory");
}
#define CP_COMMIT()  asm volatile("cp.async.commit_group;\n" ::: "memory")
#define CP_WAIT1()   asm volatile("cp.async.wait_group 1;\n" ::: "memory")
#define CP_WAIT0()   asm volatile("cp.async.wait_group 0;\n" ::: "memory")

__device__ __forceinline__ uint32_t cvt01(float2 v) {
    uint32_t lo = (v.x != 0.0f) ? 0x3F80u : 0u;
    uint32_t hi = (v.y != 0.0f) ? 0x3F800000u : 0u;
    return lo | hi;
}
__device__ __forceinline__ void mma16816(float* c, const uint32_t* a,
                                         uint32_t b0, uint32_t b1) {
    asm volatile(
        "mma.sync.aligned.m16n8k16.row.col.f32.bf16.bf16.f32 "
        "{%0,%1,%2,%3}, {%4,%5,%6,%7}, {%8,%9}, {%0,%1,%2,%3};\n"
        : "+f"(c[0]), "+f"(c[1]), "+f"(c[2]), "+f"(c[3])
        : "r"(a[0]), "r"(a[1]), "r"(a[2]), "r"(a[3]), "r"(b0), "r"(b1));
}

__global__ void __launch_bounds__(THREADS, 3)
gemm_kernel(const float* __restrict__ m,
            const float* __restrict__ W2,
            const float* __restrict__ b2,
            float* __restrict__ out,
            int L) {
    extern __shared__ char sm[];
    __nv_bfloat16* Bs = (__nv_bfloat16*)(sm + BS_OFF);
    float* w2s = (float*)(sm + W2_OFF);
    float* b2s = (float*)(sm + B2_OFF);
    const uint32_t smbase = smem_u32(sm);

    const int tid  = threadIdx.x;
    const int w    = tid >> 5;
    const int lane = tid & 31;
    const int q    = lane & 3;
    const int r4   = lane >> 2;           // 0..7
    const int row0 = blockIdx.x * TILE_M;

    // cp.async assignment: thread -> row tid/2, 4 blocks of 16B
    const int arow  = tid >> 1;           // 0..127
    const int ablk0 = (tid & 1) * 4;
    const int growa = row0 + arow;
    const bool rok  = (growa < L);
    const float* asrc = m + (size_t)(rok ? growa : 0) * S;
    const int aswz  = 2 * (arow & 3);

    float cacc[5][4];
    #pragma unroll
    for (int f = 0; f < 5; f++)
        #pragma unroll
        for (int i = 0; i < 4; i++) cacc[f][i] = 0.0f;

    // issue chunk 0
    {
        const uint32_t dbase = smbase + A0_OFF + arow * 128;
        #pragma unroll
        for (int u = 0; u < 4; u++) {
            int blk = ablk0 + u;
            int s = blk * 4;
            cp_async16(dbase + (((blk ^ aswz)) << 4), asrc + s,
                       (rok && s < S) ? 16u : 0u);
        }
        CP_COMMIT();
    }

    for (int i = tid; i < HDIM * EDIM; i += THREADS) w2s[i] = W2[i];
    for (int i = tid; i < EDIM; i += THREADS) b2s[i] = b2[i];

    const int rA  = w * 16 + r4;          // warp-local A row for fragments
    const int swz = 2 * (r4 & 3);
    const int qo  = 8 * (q & 1);          // byte offset within 16B block

    for (int c8 = 0; c8 < 8; c8++) {
        __syncthreads();                   // prior Bs fully consumed
        for (int i = tid; i < NB * 16; i += THREADS) {
            int n = i >> 4, kb = (i & 15) << 4;
            const uint4* src = (const uint4*)(g_hE + n * SP + c8 * BS_K + kb);
            uint4* dst = (uint4*)((char*)Bs + n * (BS_STR * 2) + kb * 2);
            dst[0] = src[0];
            dst[1] = src[1];
        }
        __syncthreads();

        for (int j = 0; j < 8; j++) {
            const int jc = c8 * 8 + j;
            if (jc + 1 < NKCH) {
                const int kb = (jc + 1) * KCH;
                const uint32_t dbase = smbase + ((jc + 1) & 1 ? A1_OFF : A0_OFF)
                                     + arow * 128;
                #pragma unroll
                for (int u = 0; u < 4; u++) {
                    int blk = ablk0 + u;
                    int s = kb + blk * 4;
                    bool ok = rok && (s < S);
                    cp_async16(dbase + ((blk ^ aswz) << 4),
                               asrc + (ok ? s : 0), ok ? 16u : 0u);
                }
            }
            CP_COMMIT();
            CP_WAIT1();
            __syncthreads();               // chunk jc visible to all warps

            const char* abase = sm + ((jc & 1) ? A1_OFF : A0_OFF);
            #pragma unroll
            for (int ks = 0; ks < 2; ks++) {
                uint32_t a[4];
                {
                    const int blk0 = 4 * ks + (q >> 1);
                    const int blk2 = blk0 + 2;
                    float2 v0 = *(const float2*)(abase + rA * 128
                                 + ((blk0 ^ swz) << 4) + qo);
                    float2 v1 = *(const float2*)(abase + (rA + 8) * 128
                                 + ((blk0 ^ swz) << 4) + qo);
                    float2 v2 = *(const float2*)(abase + rA * 128
                                 + ((blk2 ^ swz) << 4) + qo);
                    float2 v3 = *(const float2*)(abase + (rA + 8) * 128
                                 + ((blk2 ^ swz) << 4) + qo);
                    a[0] = cvt01(v0); a[1] = cvt01(v1);
                    a[2] = cvt01(v2); a[3] = cvt01(v3);
                }
                const int kcw = 16 * j + 8 * ks + q;   // word offset in Bs row
                #pragma unroll
                for (int f = 0; f < 5; f++) {
                    const uint32_t* bp = (const uint32_t*)Bs
                                       + (8 * f + r4) * (BS_STR / 2) + kcw;
                    mma16816(cacc[f], a, bp[0], bp[4]);
                }
            }
            __syncthreads();               // safe to overwrite buf[jc&1]
        }
    }

    CP_WAIT0();
    __syncthreads();

    // epilogue: stage C per warp in (reused) A buffers, expand 16->128 dims
    float* Cw = (float*)sm + w * (16 * 40);
    #pragma unroll
    for (int f = 0; f < 5; f++) {
        const int col = 8 * f + 2 * q;
        *(float2*)(Cw + r4 * 40 + col) = make_float2(cacc[f][0], cacc[f][1]);
        *(float2*)(Cw + (r4 + 8) * 40 + col) = make_float2(cacc[f][2], cacc[f][3]);
    }
    __syncwarp();
    {
        const int row16 = lane >> 1;
        const int half  = lane & 1;
        const float* cr = Cw + row16 * 40;
        float a[HDIM];
        #pragma unroll
        for (int d = 0; d < HDIM; d++) a[d] = cr[d] + cr[HDIM + d];
        float cnt = cr[32];
        float inv = 1.0f / fmaxf(cnt, 1.0f);
        int grow = row0 + w * 16 + row16;
        if (grow < L) {
            float* o = out + (size_t)grow * EDIM + half * 64;
            const float* w2h = w2s + half * 64;
            const float* b2h = b2s + half * 64;
            #pragma unroll
            for (int e = 0; e < 16; e++) {
                float4 bv = *(const float4*)(b2h + 4 * e);
                float4 sv = make_float4(cnt * bv.x, cnt * bv.y,
                                        cnt * bv.z, cnt * bv.w);
                #pragma unroll
                for (int d = 0; d < HDIM; d++) {
                    float4 wv = *(const float4*)(w2h + d * EDIM + 4 * e);
                    sv.x = fmaf(a[d], wv.x, sv.x);
                    sv.y = fmaf(a[d], wv.y, sv.y);
                    sv.z = fmaf(a[d], wv.z, sv.z);
                    sv.w = fmaf(a[d], wv.w, sv.w);
                }
                sv.x *= inv; sv.y *= inv; sv.z *= inv; sv.w *= inv;
                *(float4*)(o + 4 * e) = sv;
            }
        }
    }
}

extern "C" void kernel_launch(void* const* d_in, const int* in_sizes, int n_in,
                              void* d_out, int out_size) {
    const float* m  = (const float*)d_in[0];
    const float* W1 = (const float*)d_in[1];
    const float* b1 = (const float*)d_in[2];
    const float* W2 = (const float*)d_in[3];
    const float* b2 = (const float*)d_in[4];
    float* out = (float*)d_out;

    int L = in_sizes[0] / S;

    build_hE<<<(NB * SP + 255) / 256, 256>>>(W1, b1);

    cudaFuncSetAttribute(gemm_kernel,
                         cudaFuncAttributeMaxDynamicSharedMemorySize, SMEM_SZ);
    int grid = (L + TILE_M - 1) / TILE_M;
    gemm_kernel<<<grid, THREADS, SMEM_SZ>>>(m, W2, b2, out, L);
}